// round 12
// baseline (speedup 1.0000x reference)
#include <cuda_runtime.h>
#include <cuda_bf16.h>
#include <cstdint>

#define S 4096
#define GRID 128
#define BLOCK 512
#define NWARP 16
#define RPB 32             // rows per block
#define RPG 8              // rows per warp
#define KQ 1024            // K quarter per warp
#define ROWSTRIDE (S / 8)  // uint4 per row

// ---------------- device-global scratch ----------------
static __device__ __nv_bfloat16 g_M[(size_t)S * S];     // exp(log_trans), bf16
static __device__ float g_w[2][S];                      // ping-pong unnormalized filter
static __device__ unsigned long long g_flag[2][GRID];   // {f32 partialZ:hi, u32 gen:lo}

// ---------------- prep: M = bf16(exp(log_trans)); reset flags ----------------
__global__ void hmm_prep_kernel(const float* __restrict__ log_trans) {
    size_t gtid = (size_t)blockIdx.x * blockDim.x + threadIdx.x;
    if (gtid < 2 * GRID) g_flag[gtid / GRID][gtid % GRID] = 0ull;
    const size_t n4 = (size_t)S * S / 4;
    const size_t stride = (size_t)gridDim.x * blockDim.x;
    for (size_t i = gtid; i < n4; i += stride) {
        float4 v = reinterpret_cast<const float4*>(log_trans)[i];
        __nv_bfloat162 lo, hi;
        lo.x = __float2bfloat16(__expf(v.x));
        lo.y = __float2bfloat16(__expf(v.y));
        hi.x = __float2bfloat16(__expf(v.z));
        hi.y = __float2bfloat16(__expf(v.w));
        reinterpret_cast<__nv_bfloat162*>(g_M)[2 * i]     = lo;
        reinterpret_cast<__nv_bfloat162*>(g_M)[2 * i + 1] = hi;
    }
}

// ---------------- helpers ----------------
__device__ __forceinline__ float warp_sum(float v) {
#pragma unroll
    for (int o = 16; o; o >>= 1) v += __shfl_xor_sync(0xffffffffu, v, o);
    return v;
}

// EXACT bf16 pair -> f32x2
__device__ __forceinline__ unsigned long long cvt2(unsigned u) {
    unsigned long long r;
    asm("mov.b64 %0, {%1, %2};" : "=l"(r) : "r"(u << 16), "r"(u & 0xffff0000u));
    return r;
}

__device__ __forceinline__ unsigned long long fma2(unsigned long long a,
                                                   unsigned long long b,
                                                   unsigned long long c) {
    unsigned long long d;
    asm("fma.rn.f32x2 %0, %1, %2, %3;" : "=l"(d) : "l"(a), "l"(b), "l"(c));
    return d;
}

__device__ __forceinline__ float f32x2_hsum(unsigned long long v) {
    unsigned lo, hi;
    asm("mov.b64 {%0, %1}, %2;" : "=r"(lo), "=r"(hi) : "l"(v));
    return __uint_as_float(lo) + __uint_as_float(hi);
}

__device__ __forceinline__ unsigned long long ldacq(const unsigned long long* p) {
    unsigned long long v;
    asm volatile("ld.acquire.gpu.global.b64 %0, [%1];" : "=l"(v) : "l"(p) : "memory");
    return v;
}
__device__ __forceinline__ void strel(unsigned long long* p, unsigned long long v) {
    asm volatile("st.release.gpu.global.b64 [%0], %1;" :: "l"(p), "l"(v) : "memory");
}
__device__ __forceinline__ void strelax(float* p, float v) {
    asm volatile("st.relaxed.gpu.global.f32 [%0], %1;" :: "l"(p), "f"(v) : "memory");
}

// Barrier + Z-reduce: WARP 0 ONLY, short post-publish window. This is the
// only sync topology that survived five experiments (R3/R5/R7/R10/R11 all
// showed: any additional concurrent spinners starve the critical-path
// stores). Ping-pong slots make exact-match spin deadlock-free (slot of gen
// is rewritten only at gen+2, which requires all blocks past poll(gen)).
__device__ __forceinline__ float poll_all(unsigned gen, int lane) {
    const unsigned long long* base = g_flag[gen & 1];
    unsigned long long x0, x1, x2, x3;
    for (;;) {
        x0 = ldacq(base + lane);
        x1 = ldacq(base + lane + 32);
        x2 = ldacq(base + lane + 64);
        x3 = ldacq(base + lane + 96);
        if (((unsigned)x0 == gen) & ((unsigned)x1 == gen) &
            ((unsigned)x2 == gen) & ((unsigned)x3 == gen)) break;
    }
    float z = __uint_as_float((unsigned)(x0 >> 32)) +
              __uint_as_float((unsigned)(x1 >> 32)) +
              __uint_as_float((unsigned)(x2 >> 32)) +
              __uint_as_float((unsigned)(x3 >> 32));
    return warp_sum(z);
}

// ---------------- persistent forward-filter kernel ----------------
__global__ void __launch_bounds__(BLOCK, 1) hmm_main_kernel(
    const float* __restrict__ log_M0,
    const float* __restrict__ log_emit,
    const int*   __restrict__ Tptr,
    float*       __restrict__ out)
{
    __shared__ float sw[S];                       // staged w (linear space)
    __shared__ __align__(16) float s_red[RPB][4];

    const int tid  = threadIdx.x;
    const int lane = tid & 31;
    const int warp = tid >> 5;
    const int g    = warp >> 2;   // row group 0..3
    const int q    = warp & 3;    // K quarter 0..3
    const int bid  = blockIdx.x;
    const int T    = *Tptr;

    const int r0 = bid * RPB;
    const uint4* A = reinterpret_cast<const uint4*>(
        g_M + (size_t)(r0 + g * RPG) * S + q * KQ);
    const float* swq = sw + q * KQ;

    double lik = 0.0;
    float invZ = 0.f;

    // ---- t = 0 ----
    if (warp == 0) {
        int row = r0 + lane;
        float v = __expf(__ldcg(log_M0 + row) + __ldcg(log_emit + row));
        strelax(&g_w[0][row], v);
        float part = warp_sum(v);
        __syncwarp();
        if (lane == 0)
            strel(&g_flag[1][bid],
                  ((unsigned long long)__float_as_uint(part) << 32) | 1u);
        float Z = poll_all(1u, lane);
        invZ = 1.0f / Z;
        if (bid == 0 && tid == 0) lik += (double)logf(Z);
    }
    __syncthreads();   // others wait for warp 0's poll (w0 globally visible)

    for (int t = 1; t <= T; ++t) {
        const int cur = t & 1, prev = cur ^ 1;
        const unsigned gen = (unsigned)(t + 1);

        // prefetch streamed rows (6,7) at loop TOP: ~260cyc L2 latency hides
        // under the sw copy + barrier below; cannot delay the flag store.
        uint4 pf[8];
#pragma unroll
        for (int c = 0; c < 4; ++c) {
            float4 t6 = __ldcg(reinterpret_cast<const float4*>(A) + 6 * ROWSTRIDE + c * 32 + lane);
            float4 t7 = __ldcg(reinterpret_cast<const float4*>(A) + 7 * ROWSTRIDE + c * 32 + lane);
            pf[c]     = *reinterpret_cast<uint4*>(&t6);
            pf[4 + c] = *reinterpret_cast<uint4*>(&t7);
        }

        // emit prefetch (warp 0 only; consumed in epilogue)
        float em = 0.f;
        if (warp == 0) em = __ldcg(log_emit + (size_t)t * S + r0 + lane);

        // broadcast w_{t-1} into smem (each warp copies its 1/16 slice)
        {
            int j = warp * 64 + lane;
            float4 a = __ldcg(reinterpret_cast<const float4*>(g_w[prev]) + j);
            reinterpret_cast<float4*>(sw)[j] = a;
            j += 32;
            float4 b = __ldcg(reinterpret_cast<const float4*>(g_w[prev]) + j);
            reinterpret_cast<float4*>(sw)[j] = b;
        }
        __syncthreads();

        // --- dot: rows 0..5 from L1-pinned M (192KB/SM), rows 6..7 from
        // prefetch registers. Uniform latency profile across warps. ---
        unsigned long long acc[8] = {0ull, 0ull, 0ull, 0ull, 0ull, 0ull, 0ull, 0ull};
#pragma unroll
        for (int c = 0; c < 4; ++c) {
            const int kb = c * 32 + lane;
            const ulonglong2 w01 = *reinterpret_cast<const ulonglong2*>(swq + c * 256 + lane * 8);
            const ulonglong2 w23 = *reinterpret_cast<const ulonglong2*>(swq + c * 256 + lane * 8 + 4);
#pragma unroll
            for (int r = 0; r < 6; ++r) {
                uint4 a = A[r * ROWSTRIDE + kb];
                acc[r] = fma2(cvt2(a.x), w01.x, acc[r]);
                acc[r] = fma2(cvt2(a.y), w01.y, acc[r]);
                acc[r] = fma2(cvt2(a.z), w23.x, acc[r]);
                acc[r] = fma2(cvt2(a.w), w23.y, acc[r]);
            }
            {
                uint4 a = pf[c];
                acc[6] = fma2(cvt2(a.x), w01.x, acc[6]);
                acc[6] = fma2(cvt2(a.y), w01.y, acc[6]);
                acc[6] = fma2(cvt2(a.z), w23.x, acc[6]);
                acc[6] = fma2(cvt2(a.w), w23.y, acc[6]);
                uint4 b = pf[4 + c];
                acc[7] = fma2(cvt2(b.x), w01.x, acc[7]);
                acc[7] = fma2(cvt2(b.y), w01.y, acc[7]);
                acc[7] = fma2(cvt2(b.z), w23.x, acc[7]);
                acc[7] = fma2(cvt2(b.w), w23.y, acc[7]);
            }
        }

#pragma unroll
        for (int r = 0; r < 8; ++r) {
            float s = warp_sum(f32x2_hsum(acc[r]));
            if (lane == 0) s_red[g * RPG + r][q] = s;
        }
        __syncthreads();

        // epilogue + publish + barrier: warp 0 only; others park at bar.sync
        if (warp == 0) {
            float4 p = *reinterpret_cast<const float4*>(s_red[lane]);
            float dotv = (p.x + p.y) + (p.z + p.w);
            float v = dotv * __expf(em) * invZ;
            strelax(&g_w[cur][r0 + lane], v);
            float part = warp_sum(v);
            __syncwarp();
            if (lane == 0)
                strel(&g_flag[gen & 1][bid],
                      ((unsigned long long)__float_as_uint(part) << 32) | gen);
            float Z = poll_all(gen, lane);
            invZ = 1.0f / Z;
            if (bid == 0 && tid == 0) lik += (double)logf(Z);
        }
        __syncthreads();
    }

    if (bid == 0 && tid == 0) out[0] = (float)lik;
}

// ---------------- launch ----------------
extern "C" void kernel_launch(void* const* d_in, const int* in_sizes, int n_in,
                              void* d_out, int out_size) {
    const float* log_M0    = (const float*)d_in[0];
    const float* log_trans = (const float*)d_in[1];
    const float* log_emit  = (const float*)d_in[2];
    const int*   Tptr      = (const int*)d_in[3];
    float* out = (float*)d_out;

    // THE single change vs R9: minimize the smem carveout so L1D ~= 196KB
    // and the 192KB of pinned M rows actually stays resident.
    cudaFuncSetAttribute(hmm_main_kernel,
                         cudaFuncAttributePreferredSharedMemoryCarveout, 8);

    hmm_prep_kernel<<<2048, 256>>>(log_trans);
    hmm_main_kernel<<<GRID, BLOCK>>>(log_M0, log_emit, Tptr, out);
}

// round 13
// speedup vs baseline: 1.0137x; 1.0137x over previous
#include <cuda_runtime.h>
#include <cuda_bf16.h>
#include <cstdint>

#define S 4096
#define GRID 128
#define BLOCK 512
#define NWARP 16
#define RPB 32             // rows per block
#define RPG 8              // rows per warp
#define KQ 1024            // K quarter per warp
#define ROWSTRIDE (S / 8)  // uint4 per row (8 bf16 per uint4)

// ---------------- device-global scratch ----------------
static __device__ __nv_bfloat16 g_M[(size_t)S * S];     // exp(log_trans), bf16
static __device__ unsigned short g_wb[2][S];            // ping-pong w, bf16 bits
static __device__ unsigned long long g_flag[2][GRID];   // {f32 partialZ:hi, u32 gen:lo}

// ---------------- prep: M = bf16(exp(log_trans)); reset flags ----------------
__global__ void hmm_prep_kernel(const float* __restrict__ log_trans) {
    size_t gtid = (size_t)blockIdx.x * blockDim.x + threadIdx.x;
    if (gtid < 2 * GRID) g_flag[gtid / GRID][gtid % GRID] = 0ull;
    const size_t n4 = (size_t)S * S / 4;
    const size_t stride = (size_t)gridDim.x * blockDim.x;
    for (size_t i = gtid; i < n4; i += stride) {
        float4 v = reinterpret_cast<const float4*>(log_trans)[i];
        __nv_bfloat162 lo, hi;
        lo.x = __float2bfloat16(__expf(v.x));
        lo.y = __float2bfloat16(__expf(v.y));
        hi.x = __float2bfloat16(__expf(v.z));
        hi.y = __float2bfloat16(__expf(v.w));
        reinterpret_cast<__nv_bfloat162*>(g_M)[2 * i]     = lo;
        reinterpret_cast<__nv_bfloat162*>(g_M)[2 * i + 1] = hi;
    }
}

// ---------------- helpers ----------------
__device__ __forceinline__ float warp_sum(float v) {
#pragma unroll
    for (int o = 16; o; o >>= 1) v += __shfl_xor_sync(0xffffffffu, v, o);
    return v;
}

// EXACT bf16 pair -> f32x2 (used only once per 8-term chunk now)
__device__ __forceinline__ unsigned long long cvt2(unsigned u) {
    unsigned long long r;
    asm("mov.b64 %0, {%1, %2};" : "=l"(r) : "r"(u << 16), "r"(u & 0xffff0000u));
    return r;
}
__device__ __forceinline__ unsigned mul_bf2(unsigned a, unsigned b) {
    unsigned d;
    asm("mul.bf16x2 %0, %1, %2;" : "=r"(d) : "r"(a), "r"(b));
    return d;
}
__device__ __forceinline__ unsigned fma_bf2(unsigned a, unsigned b, unsigned c) {
    unsigned d;
    asm("fma.rn.bf16x2 %0, %1, %2, %3;" : "=r"(d) : "r"(a), "r"(b), "r"(c));
    return d;
}
__device__ __forceinline__ unsigned long long add2(unsigned long long a,
                                                   unsigned long long b) {
    unsigned long long d;
    asm("add.rn.f32x2 %0, %1, %2;" : "=l"(d) : "l"(a), "l"(b));
    return d;
}
__device__ __forceinline__ float f32x2_hsum(unsigned long long v) {
    unsigned lo, hi;
    asm("mov.b64 {%0, %1}, %2;" : "=r"(lo), "=r"(hi) : "l"(v));
    return __uint_as_float(lo) + __uint_as_float(hi);
}

__device__ __forceinline__ unsigned long long ldacq(const unsigned long long* p) {
    unsigned long long v;
    asm volatile("ld.acquire.gpu.global.b64 %0, [%1];" : "=l"(v) : "l"(p) : "memory");
    return v;
}
__device__ __forceinline__ void strel(unsigned long long* p, unsigned long long v) {
    asm volatile("st.release.gpu.global.b64 [%0], %1;" :: "l"(p), "l"(v) : "memory");
}
__device__ __forceinline__ void strelax16(unsigned short* p, unsigned short v) {
    asm volatile("st.relaxed.gpu.global.b16 [%0], %1;" :: "l"(p), "h"(v) : "memory");
}
__device__ __forceinline__ uint4 ldcg4(const void* p) {
    uint4 v;
    asm volatile("ld.global.cg.v4.b32 {%0,%1,%2,%3}, [%4];"
                 : "=r"(v.x), "=r"(v.y), "=r"(v.z), "=r"(v.w) : "l"(p));
    return v;
}

// Barrier + Z-reduce: WARP 0 ONLY, short post-publish window (the only sync
// topology that survived R3/R5/R7/R10/R11). Ping-pong slots keep exact-match
// spin deadlock-free (slot of gen rewritten only at gen+2).
__device__ __forceinline__ float poll_all(unsigned gen, int lane) {
    const unsigned long long* base = g_flag[gen & 1];
    unsigned long long x0, x1, x2, x3;
    for (;;) {
        x0 = ldacq(base + lane);
        x1 = ldacq(base + lane + 32);
        x2 = ldacq(base + lane + 64);
        x3 = ldacq(base + lane + 96);
        if (((unsigned)x0 == gen) & ((unsigned)x1 == gen) &
            ((unsigned)x2 == gen) & ((unsigned)x3 == gen)) break;
    }
    float z = __uint_as_float((unsigned)(x0 >> 32)) +
              __uint_as_float((unsigned)(x1 >> 32)) +
              __uint_as_float((unsigned)(x2 >> 32)) +
              __uint_as_float((unsigned)(x3 >> 32));
    return warp_sum(z);
}

// ---------------- persistent forward-filter kernel ----------------
__global__ void __launch_bounds__(BLOCK, 1) hmm_main_kernel(
    const float* __restrict__ log_M0,
    const float* __restrict__ log_emit,
    const int*   __restrict__ Tptr,
    float*       __restrict__ out)
{
    __shared__ __align__(16) unsigned sw2[S / 2];   // staged w, bf16x2 (8KB)
    __shared__ __align__(16) float s_red[RPB][4];

    const int tid  = threadIdx.x;
    const int lane = tid & 31;
    const int warp = tid >> 5;
    const int g    = warp >> 2;   // row group 0..3
    const int q    = warp & 3;    // K quarter 0..3
    const int bid  = blockIdx.x;
    const int T    = *Tptr;

    const int r0 = bid * RPB;
    const uint4* A = reinterpret_cast<const uint4*>(
        g_M + (size_t)(r0 + g * RPG) * S + q * KQ);
    const uint4* swq4 = reinterpret_cast<const uint4*>(sw2) + q * 128;

    double lik = 0.0;
    float invZ = 0.f;

    // ---- t = 0: w0 = exp(log_M0 + log_emit[0]) -> bf16 ----
    if (warp == 0) {
        int row = r0 + lane;
        float v = __expf(__ldcg(log_M0 + row) + __ldcg(log_emit + row));
        strelax16(&g_wb[0][row], (unsigned short)__bfloat16_as_ushort(__float2bfloat16(v)));
        float part = warp_sum(v);
        __syncwarp();
        if (lane == 0)
            strel(&g_flag[1][bid],
                  ((unsigned long long)__float_as_uint(part) << 32) | 1u);
        float Z = poll_all(1u, lane);
        invZ = 1.0f / Z;
        if (bid == 0 && tid == 0) lik += (double)logf(Z);
    }
    __syncthreads();   // others wait for warp 0's poll (w0 globally visible)

    for (int t = 1; t <= T; ++t) {
        const int cur = t & 1, prev = cur ^ 1;
        const unsigned gen = (unsigned)(t + 1);

        // prefetch streamed rows (6,7) at loop TOP (R9-proven placement)
        uint4 pf[8];
#pragma unroll
        for (int c = 0; c < 4; ++c) {
            pf[c]     = ldcg4(A + 6 * ROWSTRIDE + c * 32 + lane);
            pf[4 + c] = ldcg4(A + 7 * ROWSTRIDE + c * 32 + lane);
        }

        // emit prefetch (warp 0 only; consumed in epilogue)
        float em = 0.f;
        if (warp == 0) em = __ldcg(log_emit + (size_t)t * S + r0 + lane);

        // stage w_{t-1} (bf16): one uint4 per thread, zero conversions
        reinterpret_cast<uint4*>(sw2)[tid] =
            ldcg4(reinterpret_cast<const uint4*>(g_wb[prev]) + tid);
        __syncthreads();

        // --- dot in bf16x2 over 8-term chunks, f32x2 accumulate ---
        unsigned long long acc[8] = {0ull, 0ull, 0ull, 0ull, 0ull, 0ull, 0ull, 0ull};
#pragma unroll
        for (int c = 0; c < 4; ++c) {
            const int kb = c * 32 + lane;
            const uint4 wq = swq4[c * 32 + lane];   // 8 bf16 of w
#pragma unroll
            for (int r = 0; r < 6; ++r) {
                uint4 a = A[r * ROWSTRIDE + kb];    // L1-pinned rows
                unsigned h = mul_bf2(a.x, wq.x);
                h = fma_bf2(a.y, wq.y, h);
                h = fma_bf2(a.z, wq.z, h);
                h = fma_bf2(a.w, wq.w, h);
                acc[r] = add2(acc[r], cvt2(h));
            }
            {
                unsigned h = mul_bf2(pf[c].x, wq.x);
                h = fma_bf2(pf[c].y, wq.y, h);
                h = fma_bf2(pf[c].z, wq.z, h);
                h = fma_bf2(pf[c].w, wq.w, h);
                acc[6] = add2(acc[6], cvt2(h));
                unsigned h2 = mul_bf2(pf[4 + c].x, wq.x);
                h2 = fma_bf2(pf[4 + c].y, wq.y, h2);
                h2 = fma_bf2(pf[4 + c].z, wq.z, h2);
                h2 = fma_bf2(pf[4 + c].w, wq.w, h2);
                acc[7] = add2(acc[7], cvt2(h2));
            }
        }

#pragma unroll
        for (int r = 0; r < 8; ++r) {
            float s = warp_sum(f32x2_hsum(acc[r]));
            if (lane == 0) s_red[g * RPG + r][q] = s;
        }
        __syncthreads();

        // epilogue + publish + barrier: warp 0 only; others park at bar.sync
        if (warp == 0) {
            float4 p = *reinterpret_cast<const float4*>(s_red[lane]);
            float dotv = (p.x + p.y) + (p.z + p.w);
            float v = dotv * __expf(em) * invZ;
            strelax16(&g_wb[cur][r0 + lane],
                      (unsigned short)__bfloat16_as_ushort(__float2bfloat16(v)));
            float part = warp_sum(v);
            __syncwarp();
            if (lane == 0)
                strel(&g_flag[gen & 1][bid],
                      ((unsigned long long)__float_as_uint(part) << 32) | gen);
            float Z = poll_all(gen, lane);
            invZ = 1.0f / Z;
            if (bid == 0 && tid == 0) lik += (double)logf(Z);
        }
        __syncthreads();
    }

    if (bid == 0 && tid == 0) out[0] = (float)lik;
}

// ---------------- launch ----------------
extern "C" void kernel_launch(void* const* d_in, const int* in_sizes, int n_in,
                              void* d_out, int out_size) {
    const float* log_M0    = (const float*)d_in[0];
    const float* log_trans = (const float*)d_in[1];
    const float* log_emit  = (const float*)d_in[2];
    const int*   Tptr      = (const int*)d_in[3];
    float* out = (float*)d_out;

    hmm_prep_kernel<<<2048, 256>>>(log_trans);
    hmm_main_kernel<<<GRID, BLOCK>>>(log_M0, log_emit, Tptr, out);
}

// round 14
// speedup vs baseline: 1.4274x; 1.4082x over previous
#include <cuda_runtime.h>
#include <cuda_bf16.h>
#include <cstdint>

#define S 4096
#define GRID 128
#define BLOCK 512
#define NWARP 16
#define RPB 32             // rows per block
#define RPG 8              // rows per warp
#define KQ 1024            // K quarter per warp
#define ROWSTRIDE (S / 8)  // uint4 per row

// ---------------- device-global scratch ----------------
static __device__ __nv_bfloat16 g_M[(size_t)S * S];     // exp(log_trans), bf16
static __device__ float g_w[2][S];                      // ping-pong unnormalized filter
static __device__ unsigned long long g_flag[2][GRID];   // {f32 partialZ:hi, u32 gen:lo}
static __device__ float g_zs[4096];                     // per-step Z (block 0 writes)

// ---------------- prep: M = bf16(exp(log_trans)); reset flags ----------------
__global__ void hmm_prep_kernel(const float* __restrict__ log_trans) {
    size_t gtid = (size_t)blockIdx.x * blockDim.x + threadIdx.x;
    if (gtid < 2 * GRID) g_flag[gtid / GRID][gtid % GRID] = 0ull;
    const size_t n4 = (size_t)S * S / 4;
    const size_t stride = (size_t)gridDim.x * blockDim.x;
    for (size_t i = gtid; i < n4; i += stride) {
        float4 v = reinterpret_cast<const float4*>(log_trans)[i];
        __nv_bfloat162 lo, hi;
        lo.x = __float2bfloat16(__expf(v.x));
        lo.y = __float2bfloat16(__expf(v.y));
        hi.x = __float2bfloat16(__expf(v.z));
        hi.y = __float2bfloat16(__expf(v.w));
        reinterpret_cast<__nv_bfloat162*>(g_M)[2 * i]     = lo;
        reinterpret_cast<__nv_bfloat162*>(g_M)[2 * i + 1] = hi;
    }
}

// ---------------- helpers ----------------
__device__ __forceinline__ float warp_sum(float v) {
#pragma unroll
    for (int o = 16; o; o >>= 1) v += __shfl_xor_sync(0xffffffffu, v, o);
    return v;
}
__device__ __forceinline__ double warp_sum_d(double v) {
#pragma unroll
    for (int o = 16; o; o >>= 1) v += __shfl_xor_sync(0xffffffffu, v, o);
    return v;
}

// EXACT bf16 pair -> f32x2
__device__ __forceinline__ unsigned long long cvt2(unsigned u) {
    unsigned long long r;
    asm("mov.b64 %0, {%1, %2};" : "=l"(r) : "r"(u << 16), "r"(u & 0xffff0000u));
    return r;
}
__device__ __forceinline__ unsigned long long fma2(unsigned long long a,
                                                   unsigned long long b,
                                                   unsigned long long c) {
    unsigned long long d;
    asm("fma.rn.f32x2 %0, %1, %2, %3;" : "=l"(d) : "l"(a), "l"(b), "l"(c));
    return d;
}
__device__ __forceinline__ float f32x2_hsum(unsigned long long v) {
    unsigned lo, hi;
    asm("mov.b64 {%0, %1}, %2;" : "=r"(lo), "=r"(hi) : "l"(v));
    return __uint_as_float(lo) + __uint_as_float(hi);
}

__device__ __forceinline__ unsigned long long ldacq(const unsigned long long* p) {
    unsigned long long v;
    asm volatile("ld.acquire.gpu.global.b64 %0, [%1];" : "=l"(v) : "l"(p) : "memory");
    return v;
}
__device__ __forceinline__ void strel(unsigned long long* p, unsigned long long v) {
    asm volatile("st.release.gpu.global.b64 [%0], %1;" :: "l"(p), "l"(v) : "memory");
}
__device__ __forceinline__ void strelax(float* p, float v) {
    asm volatile("st.relaxed.gpu.global.f32 [%0], %1;" :: "l"(p), "f"(v) : "memory");
}

// Barrier + Z-reduce: WARP 0 ONLY, short post-publish window — the only
// sync topology that survived R3/R5/R7/R10/R11. Ping-pong slots keep the
// exact-match spin deadlock-free (slot of gen rewritten only at gen+2).
__device__ __forceinline__ float poll_all(unsigned gen, int lane) {
    const unsigned long long* base = g_flag[gen & 1];
    unsigned long long x0, x1, x2, x3;
    for (;;) {
        x0 = ldacq(base + lane);
        x1 = ldacq(base + lane + 32);
        x2 = ldacq(base + lane + 64);
        x3 = ldacq(base + lane + 96);
        if (((unsigned)x0 == gen) & ((unsigned)x1 == gen) &
            ((unsigned)x2 == gen) & ((unsigned)x3 == gen)) break;
    }
    float z = __uint_as_float((unsigned)(x0 >> 32)) +
              __uint_as_float((unsigned)(x1 >> 32)) +
              __uint_as_float((unsigned)(x2 >> 32)) +
              __uint_as_float((unsigned)(x3 >> 32));
    return warp_sum(z);
}

// ---------------- persistent forward-filter kernel ----------------
__global__ void __launch_bounds__(BLOCK, 1) hmm_main_kernel(
    const float* __restrict__ log_M0,
    const float* __restrict__ log_emit,
    const int*   __restrict__ Tptr,
    float*       __restrict__ out)
{
    __shared__ float sw[S];                       // staged w (linear space)
    __shared__ __align__(16) float s_red[RPB][4];
    __shared__ double s_dred[NWARP];

    const int tid  = threadIdx.x;
    const int lane = tid & 31;
    const int warp = tid >> 5;
    const int g    = warp >> 2;   // row group 0..3
    const int q    = warp & 3;    // K quarter 0..3
    const int bid  = blockIdx.x;
    const int T    = *Tptr;

    const int r0 = bid * RPB;
    const uint4* A = reinterpret_cast<const uint4*>(
        g_M + (size_t)(r0 + g * RPG) * S + q * KQ);
    const float* swq = sw + q * KQ;

    float invZ = 0.f;

    // ---- t = 0 ----
    if (warp == 0) {
        int row = r0 + lane;
        float v = __expf(__ldcg(log_M0 + row) + __ldcg(log_emit + row));
        strelax(&g_w[0][row], v);
        float part = warp_sum(v);
        __syncwarp();
        if (lane == 0)
            strel(&g_flag[1][bid],
                  ((unsigned long long)__float_as_uint(part) << 32) | 1u);
        float Z = poll_all(1u, lane);
        invZ = 1.0f / Z;
        if (bid == 0 && lane == 0) strelax(&g_zs[0], Z);   // raw Z, no logf in-loop
    }
    __syncthreads();   // others wait for warp 0's poll (w0 globally visible)

    for (int t = 1; t <= T; ++t) {
        const int cur = t & 1, prev = cur ^ 1;
        const unsigned gen = (unsigned)(t + 1);

        // prefetch streamed rows (6,7) at loop TOP: ~260cyc L2 latency hides
        // under the sw copy + barrier below; cannot delay the flag store.
        uint4 pf[8];
#pragma unroll
        for (int c = 0; c < 4; ++c) {
            float4 t6 = __ldcg(reinterpret_cast<const float4*>(A) + 6 * ROWSTRIDE + c * 32 + lane);
            float4 t7 = __ldcg(reinterpret_cast<const float4*>(A) + 7 * ROWSTRIDE + c * 32 + lane);
            pf[c]     = *reinterpret_cast<uint4*>(&t6);
            pf[4 + c] = *reinterpret_cast<uint4*>(&t7);
        }

        // emit prefetch (warp 0 only; consumed in epilogue)
        float em = 0.f;
        if (warp == 0) em = __ldcg(log_emit + (size_t)t * S + r0 + lane);

        // broadcast w_{t-1} into smem (each warp copies its 1/16 slice)
        {
            int j = warp * 64 + lane;
            float4 a = __ldcg(reinterpret_cast<const float4*>(g_w[prev]) + j);
            reinterpret_cast<float4*>(sw)[j] = a;
            j += 32;
            float4 b = __ldcg(reinterpret_cast<const float4*>(g_w[prev]) + j);
            reinterpret_cast<float4*>(sw)[j] = b;
        }
        __syncthreads();

        // --- dot: rows 0..5 from L1-pinned M (192KB/SM), rows 6..7 from
        // prefetch registers. Uniform latency profile across warps. ---
        unsigned long long acc[8] = {0ull, 0ull, 0ull, 0ull, 0ull, 0ull, 0ull, 0ull};
#pragma unroll
        for (int c = 0; c < 4; ++c) {
            const int kb = c * 32 + lane;
            const ulonglong2 w01 = *reinterpret_cast<const ulonglong2*>(swq + c * 256 + lane * 8);
            const ulonglong2 w23 = *reinterpret_cast<const ulonglong2*>(swq + c * 256 + lane * 8 + 4);
#pragma unroll
            for (int r = 0; r < 6; ++r) {
                uint4 a = A[r * ROWSTRIDE + kb];
                acc[r] = fma2(cvt2(a.x), w01.x, acc[r]);
                acc[r] = fma2(cvt2(a.y), w01.y, acc[r]);
                acc[r] = fma2(cvt2(a.z), w23.x, acc[r]);
                acc[r] = fma2(cvt2(a.w), w23.y, acc[r]);
            }
            {
                uint4 a = pf[c];
                acc[6] = fma2(cvt2(a.x), w01.x, acc[6]);
                acc[6] = fma2(cvt2(a.y), w01.y, acc[6]);
                acc[6] = fma2(cvt2(a.z), w23.x, acc[6]);
                acc[6] = fma2(cvt2(a.w), w23.y, acc[6]);
                uint4 b = pf[4 + c];
                acc[7] = fma2(cvt2(b.x), w01.x, acc[7]);
                acc[7] = fma2(cvt2(b.y), w01.y, acc[7]);
                acc[7] = fma2(cvt2(b.z), w23.x, acc[7]);
                acc[7] = fma2(cvt2(b.w), w23.y, acc[7]);
            }
        }

#pragma unroll
        for (int r = 0; r < 8; ++r) {
            float s = warp_sum(f32x2_hsum(acc[r]));
            if (lane == 0) s_red[g * RPG + r][q] = s;
        }
        __syncthreads();

        // epilogue + publish + barrier: warp 0 only; others park at bar.sync.
        // NO logf / double math in-loop: block 0 just dumps raw Z_t (one
        // relaxed store off the chain) — kills the systematic bid-0 straggler.
        if (warp == 0) {
            float4 p = *reinterpret_cast<const float4*>(s_red[lane]);
            float dotv = (p.x + p.y) + (p.z + p.w);
            float v = dotv * __expf(em) * invZ;
            strelax(&g_w[cur][r0 + lane], v);
            float part = warp_sum(v);
            __syncwarp();
            if (lane == 0)
                strel(&g_flag[gen & 1][bid],
                      ((unsigned long long)__float_as_uint(part) << 32) | gen);
            float Z = poll_all(gen, lane);
            invZ = 1.0f / Z;
            if (bid == 0 && lane == 0) strelax(&g_zs[t], Z);
        }
        __syncthreads();
    }

    // ---- final: block 0 sums log(Z_t) in parallel (fixed-order, deterministic) ----
    if (bid == 0) {
        double acc = 0.0;
        for (int t = tid; t <= T; t += BLOCK)
            acc += (double)logf(g_zs[t]);     // g_zs written by this block; visible
        acc = warp_sum_d(acc);
        if (lane == 0) s_dred[warp] = acc;
        __syncthreads();
        if (warp == 0) {
            double v = (lane < NWARP) ? s_dred[lane] : 0.0;
            v = warp_sum_d(v);
            if (lane == 0) out[0] = (float)v;
        }
    }
}

// ---------------- launch ----------------
extern "C" void kernel_launch(void* const* d_in, const int* in_sizes, int n_in,
                              void* d_out, int out_size) {
    const float* log_M0    = (const float*)d_in[0];
    const float* log_trans = (const float*)d_in[1];
    const float* log_emit  = (const float*)d_in[2];
    const int*   Tptr      = (const int*)d_in[3];
    float* out = (float*)d_out;

    hmm_prep_kernel<<<2048, 256>>>(log_trans);
    hmm_main_kernel<<<GRID, BLOCK>>>(log_M0, log_emit, Tptr, out);
}